// round 13
// baseline (speedup 1.0000x reference)
#include <cuda_runtime.h>
#include <cuda_fp16.h>
#include <cstdint>

#define NL 4
#define TT 64
#define PAIRS 7
#define THREADS (PAIRS * 64)         // 448: 7 warp pairs, 16 rows each
#define ROWS_CTA (PAIRS * 16)        // 112
#define BTOT 16384

// SMEM offsets
#define OFF_HX   65536u              // PAIRS * NL * 2KB (double-buffered) = 57344
#define OFF_RED  122880u
#define DSMEM    (122880 + 896 + 64)

// staged data (built by prep_kernel)
__device__ uint32_t gBF[16384];      // fp16 W fragments [l][kc][nt][lane][word] (64KB)
__device__ float    gBiasF[512];
__device__ uint32_t gXT[TT * BTOT];  // half2(x0,x1) transposed [t][b]  (4MB)
__device__ float    gWl[32];
__device__ float    gBl;

// ---------------- helpers ----------------
__device__ __forceinline__ uint32_t smem_u32(const void* p) {
    uint32_t a;
    asm("{ .reg .u64 t; cvta.to.shared.u64 t, %1; cvt.u32.u64 %0, t; }" : "=r"(a) : "l"(p));
    return a;
}
__device__ __forceinline__ void mma16816(float d[4], const uint32_t a[4], uint32_t b0, uint32_t b1) {
    asm volatile("mma.sync.aligned.m16n8k16.row.col.f32.f16.f16.f32 "
                 "{%0,%1,%2,%3}, {%4,%5,%6,%7}, {%8,%9}, {%0,%1,%2,%3};"
                 : "+f"(d[0]), "+f"(d[1]), "+f"(d[2]), "+f"(d[3])
                 : "r"(a[0]), "r"(a[1]), "r"(a[2]), "r"(a[3]), "r"(b0), "r"(b1));
}
__device__ __forceinline__ void lds64(uint32_t& a, uint32_t& b, uint32_t addr) {
    asm volatile("ld.shared.v2.u32 {%0,%1}, [%2];" : "=r"(a), "=r"(b) : "r"(addr));
}
__device__ __forceinline__ void ldf4(uint32_t* f, uint32_t addr) {
    asm volatile("ld.shared.v4.u32 {%0,%1,%2,%3}, [%4];"
                 : "=r"(f[0]), "=r"(f[1]), "=r"(f[2]), "=r"(f[3]) : "r"(addr));
}
__device__ __forceinline__ void stf4(uint32_t addr, const uint32_t* f) {
    asm volatile("st.shared.v4.u32 [%0], {%1,%2,%3,%4};"
                 :: "r"(addr), "r"(f[0]), "r"(f[1]), "r"(f[2]), "r"(f[3]) : "memory");
}
__device__ __forceinline__ void stsf(uint32_t addr, float v) {
    asm volatile("st.shared.f32 [%0], %1;" :: "r"(addr), "f"(v) : "memory");
}
__device__ __forceinline__ float ldsf(uint32_t addr) {
    float v; asm volatile("ld.shared.f32 %0, [%1];" : "=f"(v) : "r"(addr)); return v;
}
#define BARP(id) asm volatile("bar.sync %0, 64;" :: "r"(id) : "memory")

__device__ __forceinline__ uint32_t pk2h(float a, float b) {
    __half2 t = __floats2half2_rn(a, b);
    return *(uint32_t*)&t;
}
__device__ __forceinline__ uint32_t tanh2(uint32_t v) {
    uint32_t r; asm("tanh.approx.f16x2 %0, %1;" : "=r"(r) : "r"(v)); return r;
}
__device__ __forceinline__ float lo2f(uint32_t v) { return __low2float(*(__half2*)&v); }
__device__ __forceinline__ float hi2f(uint32_t v) { return __high2float(*(__half2*)&v); }
__device__ __forceinline__ uint32_t hmul2u(uint32_t a, uint32_t b) {
    __half2 r = __hmul2(*(__half2*)&a, *(__half2*)&b);
    return *(uint32_t*)&r;
}
__device__ __forceinline__ uint32_t hfma2u(uint32_t a, uint32_t b, uint32_t c) {
    __half2 r = __hfma2(*(__half2*)&a, *(__half2*)&b, *(__half2*)&c);
    return *(uint32_t*)&r;
}
__device__ __forceinline__ float sigm_ex(float v) {
    return __fdividef(1.f, 1.f + __expf(-v));
}

// ---------------- prep ----------------
__device__ __forceinline__ float getW(const float* W_ih0, const float* W_ih, const float* W_hh,
                                      int l, int n, int k) {
    if (k < 32) {
        if (l == 0) return (k < 2) ? W_ih0[n * 2 + k] : 0.f;
        return W_ih[(l - 1) * 4096 + n * 32 + k];
    }
    return W_hh[l * 4096 + n * 32 + (k - 32)];
}

__global__ void prep_kernel(const float* __restrict__ x,
                            const float* __restrict__ W_ih0, const float* __restrict__ W_ih,
                            const float* __restrict__ W_hh, const float* __restrict__ b_ih,
                            const float* __restrict__ b_hh, const float* __restrict__ W_lin,
                            const float* __restrict__ b_lin) {
    int i = blockIdx.x * blockDim.x + threadIdx.x;
    if (i < TT * BTOT) {
        int t = i >> 14, b = i & (BTOT - 1);
        gXT[i] = pk2h(x[(size_t)b * 192 + t], x[(size_t)b * 192 + 64 + t]);
    }
    if (i < 16384) {
        int word = i & 1, lane = (i >> 1) & 31, nt = (i >> 6) & 15, kc = (i >> 10) & 3, l = i >> 12;
        int n  = nt * 8 + (lane >> 2);
        int k0 = kc * 16 + (lane & 3) * 2 + word * 8;
        float w0 = getW(W_ih0, W_ih, W_hh, l, n, k0);
        float w1 = getW(W_ih0, W_ih, W_hh, l, n, k0 + 1);
        gBF[i] = pk2h(w0, w1);
    }
    if (i < 512) {
        int e = i & 1, q = (i >> 1) & 3, nt = (i >> 3) & 15, l = i >> 7;
        int n = nt * 8 + q * 2 + e;
        gBiasF[i] = b_ih[l * 128 + n] + b_hh[l * 128 + n];
    }
    if (i < 32) gWl[i] = W_lin[i];
    if (i == 0) gBl = b_lin[0];
}

// ---------------- main kernel ----------------
__global__ void __launch_bounds__(THREADS, 1)
lstm_kernel(const float* __restrict__ x_unused, float* __restrict__ out) {
    extern __shared__ __align__(16) uint4 smemraw[];
    const uint32_t smB  = smem_u32(smemraw);
    const uint32_t hxB  = smB + OFF_HX;
    const uint32_t redB = smB + OFF_RED;

    const int tid  = threadIdx.x;
    const int w    = tid >> 5;
    const int lane = tid & 31;
    const int q    = lane & 3;
    const int r    = lane >> 2;
    const int pp   = w >> 1;            // pair id
    const int wh   = w & 1;             // gate-col half; owns 16-col h chunk wh
    const int bid  = 1 + pp;            // named barrier id
    const int gb0  = blockIdx.x * ROWS_CTA + pp * 16;
    const uint32_t lane16 = (uint32_t)lane * 16u;

    // ---- stage weights into SMEM; zero hx ----
    {
        const uint4* src = (const uint4*)gBF;
        uint4* dst = (uint4*)smemraw;
        for (int i = tid; i < 4096; i += THREADS) dst[i] = src[i];
        uint4* hz = (uint4*)((char*)smemraw + OFF_HX);
        for (int i = tid; i < 57344 / 16; i += THREADS) hz[i] = make_uint4(0, 0, 0, 0);
    }
    __syncthreads();
    if (gb0 >= BTOT) return;

    // ---- bias pre-scaled into 32 half2 registers: bias2[l][jl][g4] ----
    // scale 0.5 for i,f,o gates (sigmoid-as-tanh), 1.0 for g gate.
    uint32_t bias2[NL][2][4];
#pragma unroll
    for (int l = 0; l < NL; ++l)
#pragma unroll
        for (int jl = 0; jl < 2; ++jl)
#pragma unroll
            for (int g4 = 0; g4 < 4; ++g4) {
                int jt = wh * 2 + jl;
                int idx = (((l * 16 + g4 * 4 + jt) * 4 + q) * 2);
                float s = (g4 == 2) ? 1.0f : 0.5f;
                bias2[l][jl][g4] = pk2h(s * __ldg(gBiasF + idx), s * __ldg(gBiasF + idx + 1));
            }

    float cst[NL][2][4];
#pragma unroll
    for (int l = 0; l < NL; ++l)
#pragma unroll
        for (int jl = 0; jl < 2; ++jl)
#pragma unroll
            for (int p = 0; p < 4; ++p) cst[l][jl][p] = 0.f;

    float wl[2][2];
#pragma unroll
    for (int jl = 0; jl < 2; ++jl) {
        int jt = wh * 2 + jl;
        wl[jl][0] = gWl[jt * 8 + q * 2];
        wl[jl][1] = gWl[jt * 8 + q * 2 + 1];
    }

    float prow0 = 0.f, prow8 = 0.f;
    const uint32_t hxPair = hxB + (uint32_t)pp * 8192u;   // 4 layers x 2KB (2 bufs x 1KB)
    const uint32_t h05 = pk2h(0.5f, 0.5f);
    const uint32_t h10 = pk2h(1.0f, 1.0f);

#pragma unroll 1
    for (int t = 0; t < TT; ++t) {
        const uint32_t sW = (uint32_t)(t & 1) * 1024u;        // write buf
        const uint32_t sR = sW ^ 1024u;                       // h_prev read buf

        // ---- x fragment (layer 0, kc0): rows r / r+8, k-cols 0,1 in q==0 lanes ----
        uint32_t axh[4] = {0u, 0u, 0u, 0u};
        if (q == 0) {
            axh[0] = __ldg(gXT + (size_t)t * BTOT + gb0 + r);
            axh[1] = __ldg(gXT + (size_t)t * BTOT + gb0 + r + 8);
        }

#pragma unroll
        for (int l = 0; l < NL; ++l) {
            const uint32_t hxL = hxPair + (uint32_t)l * 2048u;
            const uint32_t bL  = smB + (uint32_t)l * 16384u + (uint32_t)lane * 8u;

            float d[2][4][4];
#pragma unroll
            for (int jl = 0; jl < 2; ++jl)
#pragma unroll
                for (int g4 = 0; g4 < 4; ++g4)
#pragma unroll
                    for (int p = 0; p < 4; ++p) d[jl][g4][p] = 0.f;

            // chunk-serial A loads; B frag per (chunk, jl, g4)
#pragma unroll
            for (int c = 0; c < 4; ++c) {
                uint32_t a[4];
                int kc;
                if (c < 2) {
                    if (l == 0) {
                        if (c == 1) continue;          // l0: only x chunk (kc0)
                        a[0] = axh[0]; a[1] = axh[1]; a[2] = 0u; a[3] = 0u;
                        kc = 0;
                    } else {
                        // h_in: layer l-1's h at this step (write buf)
                        ldf4(a, hxPair + (uint32_t)(l - 1) * 2048u + sW + (uint32_t)c * 512u + lane16);
                        kc = c;
                    }
                } else {
                    // h_prev: this layer's h from previous step (read buf)
                    ldf4(a, hxL + sR + (uint32_t)(c - 2) * 512u + lane16);
                    kc = c;
                }
#pragma unroll
                for (int jl = 0; jl < 2; ++jl) {
                    const int jt = wh * 2 + jl;
#pragma unroll
                    for (int g4 = 0; g4 < 4; ++g4) {
                        uint32_t b0, b1;
                        lds64(b0, b1, bL + (uint32_t)(kc * 4096 + (g4 * 4 + jt) * 256));
                        mma16816(d[jl][g4], a, b0, b1);
                    }
                }
            }

            // ---- epilogue: bias (reg, half2) + f16x2 activations ----
            uint32_t fr[4];
#pragma unroll
            for (int jl = 0; jl < 2; ++jl) {
#pragma unroll
                for (int pr = 0; pr < 2; ++pr) {
                    const int p0 = pr * 2;
                    uint32_t ti = tanh2(hfma2u(pk2h(d[jl][0][p0], d[jl][0][p0 + 1]), h05, bias2[l][jl][0]));
                    uint32_t tf = tanh2(hfma2u(pk2h(d[jl][1][p0], d[jl][1][p0 + 1]), h05, bias2[l][jl][1]));
                    uint32_t tg = tanh2(hfma2u(pk2h(d[jl][2][p0], d[jl][2][p0 + 1]), h10, bias2[l][jl][2]));
                    uint32_t to = tanh2(hfma2u(pk2h(d[jl][3][p0], d[jl][3][p0 + 1]), h05, bias2[l][jl][3]));
                    float i0 = fmaf(0.5f, lo2f(ti), 0.5f), i1 = fmaf(0.5f, hi2f(ti), 0.5f);
                    float f0 = fmaf(0.5f, lo2f(tf), 0.5f), f1 = fmaf(0.5f, hi2f(tf), 0.5f);
                    float g0 = lo2f(tg), g1 = hi2f(tg);
                    float c0 = fmaf(f0, cst[l][jl][p0],     i0 * g0);
                    float c1 = fmaf(f1, cst[l][jl][p0 + 1], i1 * g1);
                    cst[l][jl][p0]     = c0;
                    cst[l][jl][p0 + 1] = c1;
                    uint32_t tc = tanh2(pk2h(c0, c1));
                    uint32_t o2 = hfma2u(to, h05, h05);
                    uint32_t h2 = hmul2u(o2, tc);
                    fr[jl * 2 + pr] = h2;
                    if (l == NL - 1 && t == TT - 1) {
                        float h0v = lo2f(h2), h1v = hi2f(h2);
                        if (pr == 0) {
                            prow0 = fmaf(h0v, wl[jl][0], prow0);
                            prow0 = fmaf(h1v, wl[jl][1], prow0);
                        } else {
                            prow8 = fmaf(h0v, wl[jl][0], prow8);
                            prow8 = fmaf(h1v, wl[jl][1], prow8);
                        }
                    }
                }
            }

            // ---- publish h_new to write buf; single barrier ----
            stf4(hxL + sW + (uint32_t)wh * 512u + lane16, fr);
            BARP(bid);
        }
    }

    // ---- head: out = sigmoid(h3 . Wlin + b) ----
    prow0 += __shfl_xor_sync(0xffffffffu, prow0, 1);
    prow0 += __shfl_xor_sync(0xffffffffu, prow0, 2);
    prow8 += __shfl_xor_sync(0xffffffffu, prow8, 1);
    prow8 += __shfl_xor_sync(0xffffffffu, prow8, 2);
    const uint32_t redP = redB + (uint32_t)((pp * 2 + wh) * 64);
    if (q == 0) {
        stsf(redP + (uint32_t)r * 4, prow0);
        stsf(redP + (uint32_t)(r + 8) * 4, prow8);
    }
    BARP(bid);
    if (wh == 0 && q == 0) {
        float bl = gBl;
        float v0 = ldsf(redP + (uint32_t)r * 4)       + ldsf(redP + 64u + (uint32_t)r * 4);
        float v8 = ldsf(redP + (uint32_t)(r + 8) * 4) + ldsf(redP + 64u + (uint32_t)(r + 8) * 4);
        out[gb0 + r]     = sigm_ex(v0 + bl);
        out[gb0 + r + 8] = sigm_ex(v8 + bl);
    }
}

extern "C" void kernel_launch(void* const* d_in, const int* in_sizes, int n_in,
                              void* d_out, int out_size) {
    const float* x     = (const float*)d_in[0];
    const float* W_ih0 = (const float*)d_in[1];
    const float* W_ih  = (const float*)d_in[2];
    const float* W_hh  = (const float*)d_in[3];
    const float* b_ih  = (const float*)d_in[4];
    const float* b_hh  = (const float*)d_in[5];
    const float* W_lin = (const float*)d_in[6];
    const float* b_lin = (const float*)d_in[7];

    prep_kernel<<<4096, 256>>>(x, W_ih0, W_ih, W_hh, b_ih, b_hh, W_lin, b_lin);

    cudaFuncSetAttribute(lstm_kernel, cudaFuncAttributeMaxDynamicSharedMemorySize, DSMEM);

    int blocks = (BTOT + ROWS_CTA - 1) / ROWS_CTA;    // 147
    lstm_kernel<<<blocks, THREADS, DSMEM>>>(x, (float*)d_out);
}

// round 14
// speedup vs baseline: 1.0707x; 1.0707x over previous
#include <cuda_runtime.h>
#include <cuda_fp16.h>
#include <cstdint>

#define NL 4
#define TT 64
#define PAIRS 4
#define THREADS (PAIRS * 64)         // 256: 4 warp pairs, 32 rows each
#define ROWS_CTA (PAIRS * 32)        // 128
#define BTOT 16384

// SMEM offsets
#define OFF_HX   65536u              // PAIRS * NL * 4KB (2 bufs x 2KB) = 65536
#define OFF_RED  131072u
#define DSMEM    (131072 + 1024 + 64)

// staged data (built by prep_kernel)
__device__ uint32_t gBF[16384];      // fp16 W fragments [l][kc][nt][lane][word] (64KB)
__device__ float    gBiasF[512];
__device__ float    gWl[32];
__device__ float    gBl;

// ---------------- helpers ----------------
__device__ __forceinline__ uint32_t smem_u32(const void* p) {
    uint32_t a;
    asm("{ .reg .u64 t; cvta.to.shared.u64 t, %1; cvt.u32.u64 %0, t; }" : "=r"(a) : "l"(p));
    return a;
}
__device__ __forceinline__ void mma16816(float d[4], const uint32_t a[4], uint32_t b0, uint32_t b1) {
    asm volatile("mma.sync.aligned.m16n8k16.row.col.f32.f16.f16.f32 "
                 "{%0,%1,%2,%3}, {%4,%5,%6,%7}, {%8,%9}, {%0,%1,%2,%3};"
                 : "+f"(d[0]), "+f"(d[1]), "+f"(d[2]), "+f"(d[3])
                 : "r"(a[0]), "r"(a[1]), "r"(a[2]), "r"(a[3]), "r"(b0), "r"(b1));
}
__device__ __forceinline__ void lds64(uint32_t& a, uint32_t& b, uint32_t addr) {
    asm volatile("ld.shared.v2.u32 {%0,%1}, [%2];" : "=r"(a), "=r"(b) : "r"(addr));
}
__device__ __forceinline__ void ldf4(uint32_t* f, uint32_t addr) {
    asm volatile("ld.shared.v4.u32 {%0,%1,%2,%3}, [%4];"
                 : "=r"(f[0]), "=r"(f[1]), "=r"(f[2]), "=r"(f[3]) : "r"(addr));
}
__device__ __forceinline__ void stf4(uint32_t addr, const uint32_t* f) {
    asm volatile("st.shared.v4.u32 [%0], {%1,%2,%3,%4};"
                 :: "r"(addr), "r"(f[0]), "r"(f[1]), "r"(f[2]), "r"(f[3]) : "memory");
}
__device__ __forceinline__ void stsf(uint32_t addr, float v) {
    asm volatile("st.shared.f32 [%0], %1;" :: "r"(addr), "f"(v) : "memory");
}
__device__ __forceinline__ float ldsf(uint32_t addr) {
    float v; asm volatile("ld.shared.f32 %0, [%1];" : "=f"(v) : "r"(addr)); return v;
}
#define BARP(id) asm volatile("bar.sync %0, 64;" :: "r"(id) : "memory")

__device__ __forceinline__ uint32_t pk2h(float a, float b) {
    __half2 t = __floats2half2_rn(a, b);
    return *(uint32_t*)&t;
}
__device__ __forceinline__ uint32_t tanh2(uint32_t v) {
    uint32_t r; asm("tanh.approx.f16x2 %0, %1;" : "=r"(r) : "r"(v)); return r;
}
__device__ __forceinline__ float lo2f(uint32_t v) { return __low2float(*(__half2*)&v); }
__device__ __forceinline__ float hi2f(uint32_t v) { return __high2float(*(__half2*)&v); }
__device__ __forceinline__ uint32_t hmul2u(uint32_t a, uint32_t b) {
    __half2 r = __hmul2(*(__half2*)&a, *(__half2*)&b);
    return *(uint32_t*)&r;
}
__device__ __forceinline__ uint32_t hfma2u(uint32_t a, uint32_t b, uint32_t c) {
    __half2 r = __hfma2(*(__half2*)&a, *(__half2*)&b, *(__half2*)&c);
    return *(uint32_t*)&r;
}
__device__ __forceinline__ float sigm_ex(float v) {
    return __fdividef(1.f, 1.f + __expf(-v));
}

// ---------------- prep (light, as R12) ----------------
__device__ __forceinline__ float getW(const float* W_ih0, const float* W_ih, const float* W_hh,
                                      int l, int n, int k) {
    if (k < 32) {
        if (l == 0) return (k < 2) ? W_ih0[n * 2 + k] : 0.f;
        return W_ih[(l - 1) * 4096 + n * 32 + k];
    }
    return W_hh[l * 4096 + n * 32 + (k - 32)];
}

__global__ void prep_kernel(const float* __restrict__ W_ih0, const float* __restrict__ W_ih,
                            const float* __restrict__ W_hh, const float* __restrict__ b_ih,
                            const float* __restrict__ b_hh, const float* __restrict__ W_lin,
                            const float* __restrict__ b_lin) {
    int i = blockIdx.x * blockDim.x + threadIdx.x;
    if (i < 16384) {
        int word = i & 1, lane = (i >> 1) & 31, nt = (i >> 6) & 15, kc = (i >> 10) & 3, l = i >> 12;
        int n  = nt * 8 + (lane >> 2);
        int k0 = kc * 16 + (lane & 3) * 2 + word * 8;
        float w0 = getW(W_ih0, W_ih, W_hh, l, n, k0);
        float w1 = getW(W_ih0, W_ih, W_hh, l, n, k0 + 1);
        gBF[i] = pk2h(w0, w1);
    }
    if (i < 512) {
        int e = i & 1, q = (i >> 1) & 3, nt = (i >> 3) & 15, l = i >> 7;
        int n = nt * 8 + q * 2 + e;
        gBiasF[i] = b_ih[l * 128 + n] + b_hh[l * 128 + n];
    }
    if (i < 32) gWl[i] = W_lin[i];
    if (i == 0) gBl = b_lin[0];
}

// ---------------- main kernel ----------------
__global__ void __launch_bounds__(THREADS, 1)
lstm_kernel(const float* __restrict__ x, float* __restrict__ out) {
    extern __shared__ __align__(16) uint4 smemraw[];
    const uint32_t smB  = smem_u32(smemraw);
    const uint32_t hxB  = smB + OFF_HX;
    const uint32_t redB = smB + OFF_RED;

    const int tid  = threadIdx.x;
    const int w    = tid >> 5;
    const int lane = tid & 31;
    const int q    = lane & 3;
    const int r    = lane >> 2;
    const int pp   = w >> 1;            // pair id
    const int wh   = w & 1;             // gate-col half; owns 16-col h chunk wh
    const int bid  = 1 + pp;            // named barrier id
    const int gb0  = blockIdx.x * ROWS_CTA + pp * 32;
    const uint32_t lane16 = (uint32_t)lane * 16u;

    // ---- stage weights into SMEM; zero hx ----
    {
        const uint4* src = (const uint4*)gBF;
        uint4* dst = (uint4*)smemraw;
        for (int i = tid; i < 4096; i += THREADS) dst[i] = src[i];
        uint4* hz = (uint4*)((char*)smemraw + OFF_HX);
        for (int i = tid; i < 65536 / 16; i += THREADS) hz[i] = make_uint4(0, 0, 0, 0);
    }
    __syncthreads();

    // ---- bias pre-scaled into 32 half2 registers: bias2[l][jl][g4] ----
    uint32_t bias2[NL][2][4];
#pragma unroll
    for (int l = 0; l < NL; ++l)
#pragma unroll
        for (int jl = 0; jl < 2; ++jl)
#pragma unroll
            for (int g4 = 0; g4 < 4; ++g4) {
                int jt = wh * 2 + jl;
                int idx = (((l * 16 + g4 * 4 + jt) * 4 + q) * 2);
                float s = (g4 == 2) ? 1.0f : 0.5f;
                bias2[l][jl][g4] = pk2h(s * __ldg(gBiasF + idx), s * __ldg(gBiasF + idx + 1));
            }

    float cst[NL][2][2][4];              // [l][jl][mt][p]
#pragma unroll
    for (int l = 0; l < NL; ++l)
#pragma unroll
        for (int jl = 0; jl < 2; ++jl)
#pragma unroll
            for (int mt = 0; mt < 2; ++mt)
#pragma unroll
                for (int p = 0; p < 4; ++p) cst[l][jl][mt][p] = 0.f;

    float wl[2][2];
#pragma unroll
    for (int jl = 0; jl < 2; ++jl) {
        int jt = wh * 2 + jl;
        wl[jl][0] = gWl[jt * 8 + q * 2];
        wl[jl][1] = gWl[jt * 8 + q * 2 + 1];
    }

    float prow[2][2] = {{0.f, 0.f}, {0.f, 0.f}};     // [mt][r / r+8]
    const uint32_t hxPair = hxB + (uint32_t)pp * 16384u;   // 4 layers x 4KB
    const uint32_t h05 = pk2h(0.5f, 0.5f);
    const uint32_t h10 = pk2h(1.0f, 1.0f);
    const float* xq = x + (size_t)gb0 * 192;

#pragma unroll 1
    for (int t = 0; t < TT; ++t) {
        const uint32_t sW = (uint32_t)(t & 1) * 2048u;       // write buf
        const uint32_t sR = sW ^ 2048u;                      // h_prev read buf

        // ---- x fragments (layer 0, kc0), two m-tiles; q==0 lanes hold k=0,1 ----
        uint32_t AX[2][4];
#pragma unroll
        for (int mt = 0; mt < 2; ++mt) {
            AX[mt][0] = 0u; AX[mt][1] = 0u; AX[mt][2] = 0u; AX[mt][3] = 0u;
        }
        if (q == 0) {
#pragma unroll
            for (int mt = 0; mt < 2; ++mt) {
                const float* xr = xq + (size_t)(mt * 16 + r) * 192 + t;
                AX[mt][0] = pk2h(__ldg(xr),        __ldg(xr + 64));
                AX[mt][1] = pk2h(__ldg(xr + 1536), __ldg(xr + 1600));   // row +8
            }
        }

#pragma unroll
        for (int l = 0; l < NL; ++l) {
            const uint32_t hxL = hxPair + (uint32_t)l * 4096u;
            const uint32_t bL  = smB + (uint32_t)l * 16384u + (uint32_t)lane * 8u;

            // A fragments: h_in (write buf, layer l-1) and h_prev (read buf, layer l)
            uint32_t Ain[2][2][4], Apr[2][2][4];    // [chunk][mt][4]
            if (l > 0) {
                const uint32_t base = hxPair + (uint32_t)(l - 1) * 4096u + sW;
#pragma unroll
                for (int c = 0; c < 2; ++c)
#pragma unroll
                    for (int mt = 0; mt < 2; ++mt)
                        ldf4(Ain[c][mt], base + (uint32_t)(c * 1024 + mt * 512) + lane16);
            }
#pragma unroll
            for (int c = 0; c < 2; ++c)
#pragma unroll
                for (int mt = 0; mt < 2; ++mt)
                    ldf4(Apr[c][mt], hxL + sR + (uint32_t)(c * 1024 + mt * 512) + lane16);

            uint32_t fr[2][4];                       // [mt][jl*2+pr]
#pragma unroll
            for (int jl = 0; jl < 2; ++jl) {
                const int jt = wh * 2 + jl;
                float d[2][4][4];
#pragma unroll
                for (int mt = 0; mt < 2; ++mt)
#pragma unroll
                    for (int g4 = 0; g4 < 4; ++g4)
#pragma unroll
                        for (int p = 0; p < 4; ++p) d[mt][g4][p] = 0.f;

#pragma unroll
                for (int c = 0; c < 4; ++c) {
                    const uint32_t* A0;
                    const uint32_t* A1;
                    if (c < 2) {
                        if (l == 0) {
                            if (c == 1) continue;          // l0: only x chunk (kc0)
                            A0 = AX[0]; A1 = AX[1];
                        } else {
                            A0 = Ain[c][0]; A1 = Ain[c][1];
                        }
                    } else {
                        A0 = Apr[c - 2][0]; A1 = Apr[c - 2][1];
                    }
#pragma unroll
                    for (int g4 = 0; g4 < 4; ++g4) {
                        uint32_t b0, b1;
                        lds64(b0, b1, bL + (uint32_t)(c * 4096 + (g4 * 4 + jt) * 256));
                        mma16816(d[0][g4], A0, b0, b1);
                        mma16816(d[1][g4], A1, b0, b1);
                    }
                }

                // ---- f16x2 epilogue, both m-tiles ----
#pragma unroll
                for (int mt = 0; mt < 2; ++mt) {
#pragma unroll
                    for (int pr = 0; pr < 2; ++pr) {
                        const int p0 = pr * 2;
                        uint32_t ti = tanh2(hfma2u(pk2h(d[mt][0][p0], d[mt][0][p0 + 1]), h05, bias2[l][jl][0]));
                        uint32_t tf = tanh2(hfma2u(pk2h(d[mt][1][p0], d[mt][1][p0 + 1]), h05, bias2[l][jl][1]));
                        uint32_t tg = tanh2(hfma2u(pk2h(d[mt][2][p0], d[mt][2][p0 + 1]), h10, bias2[l][jl][2]));
                        uint32_t to = tanh2(hfma2u(pk2h(d[mt][3][p0], d[mt][3][p0 + 1]), h05, bias2[l][jl][3]));
                        float i0 = fmaf(0.5f, lo2f(ti), 0.5f), i1 = fmaf(0.5f, hi2f(ti), 0.5f);
                        float f0 = fmaf(0.5f, lo2f(tf), 0.5f), f1 = fmaf(0.5f, hi2f(tf), 0.5f);
                        float g0 = lo2f(tg), g1 = hi2f(tg);
                        float c0 = fmaf(f0, cst[l][jl][mt][p0],     i0 * g0);
                        float c1 = fmaf(f1, cst[l][jl][mt][p0 + 1], i1 * g1);
                        cst[l][jl][mt][p0]     = c0;
                        cst[l][jl][mt][p0 + 1] = c1;
                        uint32_t tc = tanh2(pk2h(c0, c1));
                        uint32_t o2 = hfma2u(to, h05, h05);
                        uint32_t h2 = hmul2u(o2, tc);
                        fr[mt][jl * 2 + pr] = h2;
                        if (l == NL - 1 && t == TT - 1) {
                            float h0v = lo2f(h2), h1v = hi2f(h2);
                            prow[mt][pr] = fmaf(h0v, wl[jl][0], prow[mt][pr]);
                            prow[mt][pr] = fmaf(h1v, wl[jl][1], prow[mt][pr]);
                        }
                    }
                }
            }

            // ---- publish h_new (chunk wh, both m-tiles); single barrier ----
            stf4(hxL + sW + (uint32_t)wh * 1024u + lane16,        fr[0]);
            stf4(hxL + sW + (uint32_t)wh * 1024u + 512u + lane16, fr[1]);
            BARP(bid);
        }
    }

    // ---- head: out = sigmoid(h3 . Wlin + b) ----
#pragma unroll
    for (int mt = 0; mt < 2; ++mt)
#pragma unroll
        for (int hb = 0; hb < 2; ++hb) {
            prow[mt][hb] += __shfl_xor_sync(0xffffffffu, prow[mt][hb], 1);
            prow[mt][hb] += __shfl_xor_sync(0xffffffffu, prow[mt][hb], 2);
        }
    const uint32_t redP = redB + (uint32_t)(pp * 256);
    if (q == 0) {
#pragma unroll
        for (int mt = 0; mt < 2; ++mt) {
            stsf(redP + (uint32_t)(wh * 128 + (mt * 16 + r) * 4),     prow[mt][0]);
            stsf(redP + (uint32_t)(wh * 128 + (mt * 16 + r + 8) * 4), prow[mt][1]);
        }
    }
    BARP(bid);
    if (wh == 0 && q == 0) {
        float bl = gBl;
#pragma unroll
        for (int mt = 0; mt < 2; ++mt) {
#pragma unroll
            for (int hb = 0; hb < 2; ++hb) {
                int row = mt * 16 + r + hb * 8;
                float v = ldsf(redP + (uint32_t)(row * 4)) + ldsf(redP + (uint32_t)(128 + row * 4));
                out[gb0 + row] = sigm_ex(v + bl);
            }
        }
    }
}

extern "C" void kernel_launch(void* const* d_in, const int* in_sizes, int n_in,
                              void* d_out, int out_size) {
    const float* x     = (const float*)d_in[0];
    const float* W_ih0 = (const float*)d_in[1];
    const float* W_ih  = (const float*)d_in[2];
    const float* W_hh  = (const float*)d_in[3];
    const float* b_ih  = (const float*)d_in[4];
    const float* b_hh  = (const float*)d_in[5];
    const float* W_lin = (const float*)d_in[6];
    const float* b_lin = (const float*)d_in[7];

    prep_kernel<<<64, 256>>>(W_ih0, W_ih, W_hh, b_ih, b_hh, W_lin, b_lin);

    cudaFuncSetAttribute(lstm_kernel, cudaFuncAttributeMaxDynamicSharedMemorySize, DSMEM);

    int blocks = BTOT / ROWS_CTA;    // 128
    lstm_kernel<<<blocks, THREADS, DSMEM>>>(x, (float*)d_out);
}